// round 16
// baseline (speedup 1.0000x reference)
#include <cuda_runtime.h>
#include <cuda_fp16.h>
#include <cstdint>
#include <math.h>

// Problem constants
#define BSZ  8
#define CDIM 4096
#define TDIM 512
#define NH   8
#define HDIM 64
#define ODIM 512
#define SCALE_INV (1.0f / 22.62741699796952f)   // 1/sqrt(512)

// ---------------- scratch (static device globals; allocation-free) ----------
__device__ __align__(256) __half g_qT [BSZ * TDIM * CDIM];   // qT[b][t][c]
__device__ __align__(256) __half g_kT [BSZ * TDIM * CDIM];   // kT[b][s][c]
__device__ __align__(256) __half g_vh [BSZ * CDIM * TDIM];   // v fp16 in-layout
__device__ __align__(256) __half g_Wkh[NH * HDIM * TDIM];    // Wk fp16
__device__ __align__(256) __half g_Woh[ODIM * NH * HDIM];    // Wo fp16
__device__ __align__(256) __half g_WvT[TDIM * TDIM];         // WvT[t][j]
// g_Pd[b][t][1024]: cols 0-511 = K-half-0 partial of P, 512-1023 = half-1.
__device__ __align__(256) __half g_Pd [BSZ * TDIM * 1024];
__device__ __align__(256) float  g_U  [BSZ * TDIM * 512];    // U[b][t][h*64+e]
__device__ __align__(256) __half g_W  [BSZ * NH * HDIM * HDIM]; // W^T[e][d]
__device__ __align__(256) __half g_Z  [BSZ * TDIM * TDIM];
__device__ __align__(256) __half g_G  [BSZ * TDIM * TDIM];

// ---------------- helpers ----------------
__device__ __forceinline__ uint32_t smem_u32(const void* p) {
    uint32_t a;
    asm("{ .reg .u64 t; cvta.to.shared.u64 t, %1; cvt.u32.u64 %0, t; }" : "=r"(a) : "l"(p));
    return a;
}

__device__ __forceinline__ void cp16(uint32_t dst, const void* src) {
    asm volatile("cp.async.cg.shared.global [%0], [%1], 16;" :: "r"(dst), "l"(src));
}
#define CP_COMMIT() asm volatile("cp.async.commit_group;" ::: "memory")
#define CP_WAIT1()  asm volatile("cp.async.wait_group 1;"  ::: "memory")

__device__ __forceinline__ void mma_f16(float* c, const unsigned* a, const unsigned* b) {
    asm("mma.sync.aligned.m16n8k16.row.col.f32.f16.f16.f32 "
        "{%0,%1,%2,%3},{%4,%5,%6,%7},{%8,%9},{%0,%1,%2,%3};"
        : "+f"(c[0]), "+f"(c[1]), "+f"(c[2]), "+f"(c[3])
        : "r"(a[0]), "r"(a[1]), "r"(a[2]), "r"(a[3]),
          "r"(b[0]), "r"(b[1]));
}

__device__ __forceinline__ void ldsm4(unsigned* r, uint32_t addr) {
    asm volatile("ldmatrix.sync.aligned.m8n8.x4.shared.b16 {%0,%1,%2,%3}, [%4];"
        : "=r"(r[0]), "=r"(r[1]), "=r"(r[2]), "=r"(r[3]) : "r"(addr));
}

// XOR-swizzled smem layout: rows of 32 halves, 8-half chunks permuted by
// chunk ^ ((row>>1)&3).  Conflict-free for cp.async stores and LDSM rows.
__device__ __forceinline__ int hoff(int row, int chunk) {
    return row * 32 + ((chunk ^ ((row >> 1) & 3)) << 3);
}

// =============================================================================
// Unified fp16 GEMM engine: 128(M) x NCOLS(N) CTA tile, BK=32 (2 k16-steps),
// 256 thr, 3-stage cp.async, ldmatrix fragment loads with hoisted offsets.
// =============================================================================
template<int NCOLS, bool DHALF>
__device__ __forceinline__ void gemm_h(const __half* __restrict__ A, int lda,
                                       const __half* __restrict__ B, int ldb,
                                       unsigned kmaskB, int NC,
                                       void* __restrict__ Dv, int ldd)
{
    extern __shared__ __half smh[];
    constexpr int ASTAGE = 128 * 32;          // halves
    constexpr int BSTAGE = NCOLS * 32;
    constexpr int STAGE  = ASTAGE + BSTAGE;
    constexpr int NI     = (NCOLS == 128) ? 8 : 4;
    constexpr int NP     = NI / 2;

    const int tid  = threadIdx.x;
    const int lane = tid & 31;
    const int w    = tid >> 5;
    const int g    = lane >> 2;
    const int qd   = lane & 3;
    const int mb   = (NCOLS == 128) ? (w >> 1) * 32 : (w & 3) * 32;
    const int nb   = (NCOLS == 128) ? (w & 1) * 64 : (w >> 2) * 32;

    int aoff[2][2];
    {
        const int arow = (lane & 7) + ((lane >> 3) & 1) * 8;
        const int achk = lane >> 4;
#pragma unroll
        for (int mi = 0; mi < 2; mi++)
#pragma unroll
            for (int ks = 0; ks < 2; ks++)
                aoff[mi][ks] = hoff(mb + mi * 16 + arow, ks * 2 + achk) * 2;
    }
    int boff[NP][2];
    {
        const int brow = ((lane >> 4) << 3) + (lane & 7);
        const int bchk = (lane >> 3) & 1;
#pragma unroll
        for (int np = 0; np < NP; np++)
#pragma unroll
            for (int ks = 0; ks < 2; ks++)
                boff[np][ks] = hoff(nb + np * 16 + brow, ks * 2 + bchk) * 2;
    }

    auto issue = [&](int c) {
        __half* stA = smh + (c % 3) * STAGE;
#pragma unroll
        for (int it = 0; it < 2; it++) {
            int i = tid + it * 256;
            int row = i >> 2, kc = i & 3;
            cp16(smem_u32(stA + hoff(row, kc)),
                 A + (size_t)row * lda + (size_t)c * 32 + kc * 8);
        }
        __half* stB = stA + ASTAGE;
        unsigned koff = ((unsigned)c * 32u) & kmaskB;
#pragma unroll
        for (int it = 0; it < NCOLS / 64; it++) {
            int i = tid + it * 256;
            int row = i >> 2, kc = i & 3;
            cp16(smem_u32(stB + hoff(row, kc)),
                 B + (size_t)row * ldb + koff + kc * 8);
        }
    };

    float acc[2][NI][4];
#pragma unroll
    for (int mi = 0; mi < 2; mi++)
#pragma unroll
        for (int ni = 0; ni < NI; ni++)
#pragma unroll
            for (int r = 0; r < 4; r++) acc[mi][ni][r] = 0.f;

    issue(0); CP_COMMIT();
    issue(1); CP_COMMIT();

    const uint32_t smbase = smem_u32(smh);

    for (int c = 0; c < NC; c++) {
        CP_WAIT1();
        __syncthreads();
        const uint32_t abase = smbase + (c % 3) * (STAGE * 2);
        const uint32_t bbase = abase + ASTAGE * 2;

#pragma unroll
        for (int ks = 0; ks < 2; ks++) {
            unsigned af[2][4];
            ldsm4(af[0], abase + aoff[0][ks]);
            ldsm4(af[1], abase + aoff[1][ks]);
            unsigned bf[NI][2];
#pragma unroll
            for (int np = 0; np < NP; np++)
                ldsm4(&bf[2 * np][0], bbase + boff[np][ks]);
#pragma unroll
            for (int mi = 0; mi < 2; mi++)
#pragma unroll
                for (int ni = 0; ni < NI; ni++)
                    mma_f16(acc[mi][ni], af[mi], bf[ni]);
        }

        if (c + 2 < NC) issue(c + 2);
        CP_COMMIT();
    }

#pragma unroll
    for (int mi = 0; mi < 2; mi++)
#pragma unroll
        for (int ni = 0; ni < NI; ni++) {
            const int row = mb + mi * 16 + g;
            const int col = nb + ni * 8 + 2 * qd;
            if (DHALF) {
                __half* D = (__half*)Dv;
                *(__half2*)&D[(size_t)row * ldd + col] =
                    __floats2half2_rn(acc[mi][ni][0], acc[mi][ni][1]);
                *(__half2*)&D[(size_t)(row + 8) * ldd + col] =
                    __floats2half2_rn(acc[mi][ni][2], acc[mi][ni][3]);
            } else {
                float* D = (float*)Dv;
                *(float2*)&D[(size_t)row * ldd + col] =
                    make_float2(acc[mi][ni][0], acc[mi][ni][1]);
                *(float2*)&D[(size_t)(row + 8) * ldd + col] =
                    make_float2(acc[mi][ni][2], acc[mi][ni][3]);
            }
        }
}

// =============================================================================
// Conversion kernels
// =============================================================================
// qT[b][t][c] = fp16(q[b][c][t]) for c in [c_base, c_base+2048).
// grid (16, 32, 16).
__global__ void __launch_bounds__(256) k_cvtqk(const float* __restrict__ q,
                                               const float* __restrict__ kk_,
                                               int c_base)
{
    __shared__ float tile[64][33];
    const int z = blockIdx.z;
    const int b = z >> 1;
    const float* src = (z & 1) ? kk_ : q;
    __half* dst = (z & 1) ? g_kT : g_qT;
    const int t0 = blockIdx.x * 32;
    const int c0 = c_base + blockIdx.y * 64;
    const int tid = threadIdx.x;
    {
        const int x = tid & 31;
        const int y = tid >> 5;
#pragma unroll
        for (int j = 0; j < 8; j++) {
            int c = y + 8 * j;
            tile[c][x] = src[(size_t)b * CDIM * TDIM + (size_t)(c0 + c) * TDIM + t0 + x];
        }
    }
    __syncthreads();
    {
        const int t  = tid >> 3;
        const int c8 = (tid & 7) * 8;
        float f[8];
#pragma unroll
        for (int j = 0; j < 8; j++) f[j] = tile[c8 + j][t];
        __half2 h[4];
#pragma unroll
        for (int j = 0; j < 4; j++) h[j] = __floats2half2_rn(f[2 * j], f[2 * j + 1]);
        *(uint4*)&dst[(size_t)b * TDIM * CDIM + (size_t)(t0 + t) * CDIM + c0 + c8] =
            *(uint4*)h;
    }
}

// Merged auxiliary conversions: v, Wk, Wo linear + Wv transpose.
__global__ void __launch_bounds__(256) k_cvtaux(const float* __restrict__ v,
                                                const float* __restrict__ Wk,
                                                const float* __restrict__ Wo,
                                                const float* __restrict__ Wv)
{
    const int bx = blockIdx.x;
    const int tid = threadIdx.x;
    if (bx < 16896) {
        const float* src; __half* dst; size_t base;
        if (bx < 16384)      { src = v;  dst = g_vh;  base = (size_t)bx * 1024; }
        else if (bx < 16640) { src = Wk; dst = g_Wkh; base = (size_t)(bx - 16384) * 1024; }
        else                 { src = Wo; dst = g_Woh; base = (size_t)(bx - 16640) * 1024; }
        size_t off = base + (size_t)tid * 4;
        float4 a = *(const float4*)&src[off];
        *(__half2*)&dst[off]     = __floats2half2_rn(a.x, a.y);
        *(__half2*)&dst[off + 2] = __floats2half2_rn(a.z, a.w);
    } else {
        __shared__ float tile[64][33];
        const int idx = bx - 16896;
        const int t0 = (idx & 15) * 32;
        const int j0 = (idx >> 4) * 64;
        {
            const int x = tid & 31;
            const int y = tid >> 5;
#pragma unroll
            for (int jj = 0; jj < 8; jj++) {
                int j = y + 8 * jj;
                tile[j][x] = Wv[(size_t)(j0 + j) * TDIM + t0 + x];
            }
        }
        __syncthreads();
        {
            const int t  = tid >> 3;
            const int j8 = (tid & 7) * 8;
            float f[8];
#pragma unroll
            for (int jj = 0; jj < 8; jj++) f[jj] = tile[j8 + jj][t];
            __half2 h[4];
#pragma unroll
            for (int jj = 0; jj < 4; jj++)
                h[jj] = __floats2half2_rn(f[2 * jj], f[2 * jj + 1]);
            *(uint4*)&g_WvT[(size_t)(t0 + t) * TDIM + j0 + j8] = *(uint4*)h;
        }
    }
}

// =============================================================================
// K1: P half: g_Pd[b][t][ph*512+s] = sum_{c in half ph} qT[b][t][c] kT[b][s][c]
// One K-half per launch; grid (4, 4, 8).
// =============================================================================
__global__ void __launch_bounds__(256, 2) k_pmat(int ph)
{
    const int b  = blockIdx.z;
    const int t0 = blockIdx.y * 128;
    const int s0 = blockIdx.x * 128;
    const __half* Ab = g_qT + (size_t)b * TDIM * CDIM + (size_t)t0 * CDIM + ph * (CDIM / 2);
    const __half* Bb = g_kT + (size_t)b * TDIM * CDIM + (size_t)s0 * CDIM + ph * (CDIM / 2);
    __half* D = g_Pd + (size_t)b * TDIM * 1024 + (size_t)t0 * 1024 + ph * 512 + s0;
    gemm_h<128, true>(Ab, CDIM, Bb, CDIM, 0xffffffffu, (CDIM / 2) / 32, D, 1024);
}

// =============================================================================
// K2a: U[b][t][hp*128 + e'] = sum_{k'=0..1023} g_Pd[b][t][k'] *
//      Wk[hp*2 heads][e'][k' mod 512]        (2 heads per CTA, NCOLS=128)
// grid (4 t-tiles, 4 head-pairs, 8 b) = 128 CTAs.
// =============================================================================
__global__ void __launch_bounds__(256, 2) k_umat()
{
    const int b  = blockIdx.z;
    const int hp = blockIdx.y;
    const int t0 = blockIdx.x * 128;
    const __half* Ab = g_Pd + (size_t)b * TDIM * 1024 + (size_t)t0 * 1024;
    const __half* Bb = g_Wkh + (size_t)hp * 128 * TDIM;
    float* D = g_U + (size_t)b * TDIM * 512 + (size_t)t0 * 512 + hp * 128;
    gemm_h<128, false>(Ab, 1024, Bb, TDIM, 511u, 1024 / 32, D, 512);
}

// =============================================================================
// K2b: per (b,h): S = Wq_h @ U_h / sqrt(512); W = softmax_rows(S);
// store W^T fp16 -> g_W[bh][e][d].   U stride is now 512 (heads packed).
// =============================================================================
__global__ void __launch_bounds__(256) k_attn(const float* __restrict__ Wq)
{
    const int bh = blockIdx.x;
    const int b = bh >> 3, h = bh & 7;

    __shared__ float Ws[64][65];
    __shared__ float Us[32][68];
    __shared__ float Wqs[64][33];

    const float* Ub  = g_U + (size_t)b * TDIM * 512 + h * 64;
    const float* Wqh = Wq + (size_t)h * HDIM * TDIM;

    const int tid = threadIdx.x;
    const int tx = tid & 15, ty = tid >> 4;

    float acc[4][4];
#pragma unroll
    for (int m = 0; m < 4; m++)
#pragma unroll
        for (int n = 0; n < 4; n++) acc[m][n] = 0.f;

    for (int t0 = 0; t0 < TDIM; t0 += 32) {
#pragma unroll
        for (int i = 0; i < 2; i++) {
            int idx = tid + i * 256;
            int tl  = idx >> 4;
            int eq  = (idx & 15) * 4;
            *(float4*)&Us[tl][eq] = *(const float4*)&Ub[(size_t)(t0 + tl) * 512 + eq];
        }
#pragma unroll
        for (int i = 0; i < 2; i++) {
            int idx = tid + i * 256;
            int d   = idx >> 3;
            int tq  = (idx & 7) * 4;
            float4 a = *(const float4*)&Wqh[(size_t)d * TDIM + t0 + tq];
            Wqs[d][tq + 0] = a.x; Wqs[d][tq + 1] = a.y;
            Wqs[d][tq + 2] = a.z; Wqs[d][tq + 3] = a.w;
        }
        __syncthreads();
#pragma unroll
        for (int tl = 0; tl < 32; tl++) {
            float ra[4], rb[4];
#pragma unroll
            for (int m = 0; m < 4; m++) ra[m] = Wqs[ty * 4 + m][tl];
#pragma unroll
            for (int n = 0; n < 4; n++) rb[n] = Us[tl][tx * 4 + n];
#pragma unroll
            for (int m = 0; m < 4; m++)
#pragma unroll
                for (int n = 0; n < 4; n++) acc[m][n] += ra[m] * rb[n];
        }
        __syncthreads();
    }

#pragma unroll
    for (int m = 0; m < 4; m++)
#pragma unroll
        for (int n = 0; n < 4; n++)
            Ws[ty * 4 + m][tx * 4 + n] = acc[m][n] * SCALE_INV;
    __syncthreads();

    if (tid < 64) {
        float mx = -1e30f;
#pragma unroll 8
        for (int e = 0; e < 64; e++) mx = fmaxf(mx, Ws[tid][e]);
        float sum = 0.f;
#pragma unroll 8
        for (int e = 0; e < 64; e++) { float ex = expf(Ws[tid][e] - mx); Ws[tid][e] = ex; sum += ex; }
        float inv = 1.f / sum;
#pragma unroll 8
        for (int e = 0; e < 64; e++) Ws[tid][e] *= inv;
    }
    __syncthreads();

    __half* Wt = g_W + (size_t)bh * HDIM * HDIM;
    for (int idx = tid; idx < HDIM * HDIM; idx += 256) {
        int e = idx >> 6, d = idx & 63;
        Wt[(size_t)e * HDIM + d] = __float2half_rn(Ws[d][e]);
    }
}

// =============================================================================
// K2c: Z[b][o][h*64+e] = sum_d Wo[o][h*64+d] * W_h[d][e]
// =============================================================================
__global__ void __launch_bounds__(256, 3) k_zmat()
{
    const int bh = blockIdx.y;
    const int b = bh >> 3, h = bh & 7;
    const int o0 = blockIdx.x * 128;
    const __half* Ab = g_Woh + (size_t)o0 * (NH * HDIM) + h * HDIM;
    const __half* Bb = g_W + (size_t)bh * HDIM * HDIM;
    __half* D = g_Z + (size_t)b * TDIM * TDIM + (size_t)o0 * TDIM + h * HDIM;
    gemm_h<64, true>(Ab, NH * HDIM, Bb, HDIM, 0xffffffffu, HDIM / 32, D, TDIM);
}

// =============================================================================
// K3: G[b][o][t] = sum_j Z[b][o][j] * WvT[t][j]
// =============================================================================
__global__ void __launch_bounds__(256, 3) k_gmat()
{
    const int b  = blockIdx.z;
    const int o0 = blockIdx.y * 128;
    const int t0 = blockIdx.x * 64;
    const __half* Ab = g_Z + (size_t)b * TDIM * TDIM + (size_t)o0 * TDIM;
    const __half* Bb = g_WvT + (size_t)t0 * TDIM;
    __half* D = g_G + (size_t)b * TDIM * TDIM + (size_t)o0 * TDIM + t0;
    gemm_h<64, true>(Ab, TDIM, Bb, TDIM, 0xffffffffu, TDIM / 32, D, TDIM);
}

// =============================================================================
// K4: out[b][c][o] = sum_t vh[b][c][t] * G[b][o][t]
// =============================================================================
__global__ void __launch_bounds__(256, 2) k_out(float* __restrict__ out)
{
    const int b  = blockIdx.z;
    const int c0 = blockIdx.y * 128;
    const int o0 = blockIdx.x * 128;
    const __half* Ab = g_vh + (size_t)b * CDIM * TDIM + (size_t)c0 * TDIM;
    const __half* Bb = g_G + (size_t)b * TDIM * TDIM + (size_t)o0 * TDIM;
    float* D = out + (size_t)b * CDIM * ODIM + (size_t)c0 * ODIM + o0;
    gemm_h<128, false>(Ab, TDIM, Bb, TDIM, 0xffffffffu, TDIM / 32, D, ODIM);
}

// =============================================================================
extern "C" void kernel_launch(void* const* d_in, const int* in_sizes, int n_in,
                              void* d_out, int out_size)
{
    const float* q  = (const float*)d_in[0];
    const float* k  = (const float*)d_in[1];
    const float* v  = (const float*)d_in[2];
    const float* Wq = (const float*)d_in[3];
    const float* Wk = (const float*)d_in[4];
    const float* Wv = (const float*)d_in[5];
    const float* Wo = (const float*)d_in[6];
    float* out = (float*)d_out;
    (void)in_sizes; (void)n_in; (void)out_size;

    const int SM_128 = 3 * (128 + 128) * 32 * 2;   // 49152
    const int SM_64  = 3 * (128 + 64) * 32 * 2;    // 36864

    cudaFuncSetAttribute(k_pmat, cudaFuncAttributeMaxDynamicSharedMemorySize, SM_128);
    cudaFuncSetAttribute(k_umat, cudaFuncAttributeMaxDynamicSharedMemorySize, SM_128);
    cudaFuncSetAttribute(k_zmat, cudaFuncAttributeMaxDynamicSharedMemorySize, SM_64);
    cudaFuncSetAttribute(k_gmat, cudaFuncAttributeMaxDynamicSharedMemorySize, SM_64);
    cudaFuncSetAttribute(k_out,  cudaFuncAttributeMaxDynamicSharedMemorySize, SM_128);

    // Side stream + events (host objects; created once).
    static cudaStream_t s_side = nullptr;
    static cudaEvent_t  s_e1 = nullptr, s_e2 = nullptr, s_eaux = nullptr;
    if (s_side == nullptr) {
        cudaStreamCreateWithFlags(&s_side, cudaStreamNonBlocking);
        cudaEventCreateWithFlags(&s_e1,   cudaEventDisableTiming);
        cudaEventCreateWithFlags(&s_e2,   cudaEventDisableTiming);
        cudaEventCreateWithFlags(&s_eaux, cudaEventDisableTiming);
    }

    // Main: convert K-half 0 of q/k.
    k_cvtqk<<<dim3(16, 32, 16), 256>>>(q, k, 0);
    cudaEventRecord(s_e1, 0);

    // Side: after cvt_h0, convert K-half 1, then aux (v, Wk, Wo, Wv).
    cudaStreamWaitEvent(s_side, s_e1, 0);
    k_cvtqk<<<dim3(16, 32, 16), 256, 0, s_side>>>(q, k, CDIM / 2);
    cudaEventRecord(s_e2, s_side);
    k_cvtaux<<<17024, 256, 0, s_side>>>(v, Wk, Wo, Wv);
    cudaEventRecord(s_eaux, s_side);

    // Main: pmat half 0 (overlaps with side-stream conversions).
    k_pmat<<<dim3(4, 4, BSZ), 256, SM_128>>>(0);

    // pmat half 1 needs cvt_h1.
    cudaStreamWaitEvent(0, s_e2, 0);
    k_pmat<<<dim3(4, 4, BSZ), 256, SM_128>>>(1);

    // umat needs Wk fp16 (aux).
    cudaStreamWaitEvent(0, s_eaux, 0);
    k_umat<<<dim3(4, 4, BSZ), 256, SM_128>>>();
    k_attn<<<BSZ * NH,        256>>>(Wq);
    k_zmat<<<dim3(4, BSZ * NH), 256, SM_64>>>();
    k_gmat<<<dim3(8, 4, BSZ),   256, SM_64>>>();
    k_out <<<dim3(4, 32, BSZ),  256, SM_128>>>(out);
}

// round 17
// speedup vs baseline: 1.1070x; 1.1070x over previous
#include <cuda_runtime.h>
#include <cuda_fp16.h>
#include <cstdint>
#include <math.h>

// Problem constants
#define BSZ  8
#define CDIM 4096
#define TDIM 512
#define NH   8
#define HDIM 64
#define ODIM 512
#define SCALE_INV (1.0f / 22.62741699796952f)   // 1/sqrt(512)

// ---------------- scratch (static device globals; allocation-free) ----------
__device__ __align__(256) __half g_qT [BSZ * TDIM * CDIM];   // qT[b][t][c]
__device__ __align__(256) __half g_kT [BSZ * TDIM * CDIM];   // kT[b][s][c]
__device__ __align__(256) __half g_vh [BSZ * CDIM * TDIM];   // v fp16 in-layout
__device__ __align__(256) __half g_Wkh[NH * HDIM * TDIM];    // Wk fp16
__device__ __align__(256) __half g_Woh[ODIM * NH * HDIM];    // Wo fp16
__device__ __align__(256) __half g_WvT[TDIM * TDIM];         // WvT[t][j]
// g_Pd[b][t][1024]: cols 0-511 = K-half-0 partial of P, 512-1023 = half-1.
__device__ __align__(256) __half g_Pd [BSZ * TDIM * 1024];
__device__ __align__(256) float  g_U  [BSZ * TDIM * 512];    // U[b][t][h*64+e]
__device__ __align__(256) __half g_W  [BSZ * NH * HDIM * HDIM]; // W^T[e][d]
__device__ __align__(256) __half g_Z  [BSZ * TDIM * TDIM];
__device__ __align__(256) __half g_G  [BSZ * TDIM * TDIM];

// ---------------- helpers ----------------
__device__ __forceinline__ uint32_t smem_u32(const void* p) {
    uint32_t a;
    asm("{ .reg .u64 t; cvta.to.shared.u64 t, %1; cvt.u32.u64 %0, t; }" : "=r"(a) : "l"(p));
    return a;
}

__device__ __forceinline__ void cp16(uint32_t dst, const void* src) {
    asm volatile("cp.async.cg.shared.global [%0], [%1], 16;" :: "r"(dst), "l"(src));
}
#define CP_COMMIT() asm volatile("cp.async.commit_group;" ::: "memory")
#define CP_WAIT1()  asm volatile("cp.async.wait_group 1;"  ::: "memory")

__device__ __forceinline__ void mma_f16(float* c, const unsigned* a, const unsigned* b) {
    asm("mma.sync.aligned.m16n8k16.row.col.f32.f16.f16.f32 "
        "{%0,%1,%2,%3},{%4,%5,%6,%7},{%8,%9},{%0,%1,%2,%3};"
        : "+f"(c[0]), "+f"(c[1]), "+f"(c[2]), "+f"(c[3])
        : "r"(a[0]), "r"(a[1]), "r"(a[2]), "r"(a[3]),
          "r"(b[0]), "r"(b[1]));
}

__device__ __forceinline__ void ldsm4(unsigned* r, uint32_t addr) {
    asm volatile("ldmatrix.sync.aligned.m8n8.x4.shared.b16 {%0,%1,%2,%3}, [%4];"
        : "=r"(r[0]), "=r"(r[1]), "=r"(r[2]), "=r"(r[3]) : "r"(addr));
}

// XOR-swizzled smem layout: rows of 32 halves, 8-half chunks permuted by
// chunk ^ ((row>>1)&3).  Conflict-free for cp.async stores and LDSM rows.
__device__ __forceinline__ int hoff(int row, int chunk) {
    return row * 32 + ((chunk ^ ((row >> 1) & 3)) << 3);
}

// =============================================================================
// Unified fp16 GEMM engine: 128(M) x NCOLS(N) CTA tile, BK=32 (2 k16-steps),
// 256 thr, 3-stage cp.async, ldmatrix fragment loads with hoisted offsets.
// =============================================================================
template<int NCOLS, bool DHALF>
__device__ __forceinline__ void gemm_h(const __half* __restrict__ A, int lda,
                                       const __half* __restrict__ B, int ldb,
                                       unsigned kmaskB, int NC,
                                       void* __restrict__ Dv, int ldd)
{
    extern __shared__ __half smh[];
    constexpr int ASTAGE = 128 * 32;          // halves
    constexpr int BSTAGE = NCOLS * 32;
    constexpr int STAGE  = ASTAGE + BSTAGE;
    constexpr int NI     = (NCOLS == 128) ? 8 : 4;
    constexpr int NP     = NI / 2;

    const int tid  = threadIdx.x;
    const int lane = tid & 31;
    const int w    = tid >> 5;
    const int g    = lane >> 2;
    const int qd   = lane & 3;
    const int mb   = (NCOLS == 128) ? (w >> 1) * 32 : (w & 3) * 32;
    const int nb   = (NCOLS == 128) ? (w & 1) * 64 : (w >> 2) * 32;

    int aoff[2][2];
    {
        const int arow = (lane & 7) + ((lane >> 3) & 1) * 8;
        const int achk = lane >> 4;
#pragma unroll
        for (int mi = 0; mi < 2; mi++)
#pragma unroll
            for (int ks = 0; ks < 2; ks++)
                aoff[mi][ks] = hoff(mb + mi * 16 + arow, ks * 2 + achk) * 2;
    }
    int boff[NP][2];
    {
        const int brow = ((lane >> 4) << 3) + (lane & 7);
        const int bchk = (lane >> 3) & 1;
#pragma unroll
        for (int np = 0; np < NP; np++)
#pragma unroll
            for (int ks = 0; ks < 2; ks++)
                boff[np][ks] = hoff(nb + np * 16 + brow, ks * 2 + bchk) * 2;
    }

    auto issue = [&](int c) {
        __half* stA = smh + (c % 3) * STAGE;
#pragma unroll
        for (int it = 0; it < 2; it++) {
            int i = tid + it * 256;
            int row = i >> 2, kc = i & 3;
            cp16(smem_u32(stA + hoff(row, kc)),
                 A + (size_t)row * lda + (size_t)c * 32 + kc * 8);
        }
        __half* stB = stA + ASTAGE;
        unsigned koff = ((unsigned)c * 32u) & kmaskB;
#pragma unroll
        for (int it = 0; it < NCOLS / 64; it++) {
            int i = tid + it * 256;
            int row = i >> 2, kc = i & 3;
            cp16(smem_u32(stB + hoff(row, kc)),
                 B + (size_t)row * ldb + koff + kc * 8);
        }
    };

    float acc[2][NI][4];
#pragma unroll
    for (int mi = 0; mi < 2; mi++)
#pragma unroll
        for (int ni = 0; ni < NI; ni++)
#pragma unroll
            for (int r = 0; r < 4; r++) acc[mi][ni][r] = 0.f;

    issue(0); CP_COMMIT();
    issue(1); CP_COMMIT();

    const uint32_t smbase = smem_u32(smh);

    for (int c = 0; c < NC; c++) {
        CP_WAIT1();
        __syncthreads();
        const uint32_t abase = smbase + (c % 3) * (STAGE * 2);
        const uint32_t bbase = abase + ASTAGE * 2;

#pragma unroll
        for (int ks = 0; ks < 2; ks++) {
            unsigned af[2][4];
            ldsm4(af[0], abase + aoff[0][ks]);
            ldsm4(af[1], abase + aoff[1][ks]);
            unsigned bf[NI][2];
#pragma unroll
            for (int np = 0; np < NP; np++)
                ldsm4(&bf[2 * np][0], bbase + boff[np][ks]);
#pragma unroll
            for (int mi = 0; mi < 2; mi++)
#pragma unroll
                for (int ni = 0; ni < NI; ni++)
                    mma_f16(acc[mi][ni], af[mi], bf[ni]);
        }

        if (c + 2 < NC) issue(c + 2);
        CP_COMMIT();
    }

#pragma unroll
    for (int mi = 0; mi < 2; mi++)
#pragma unroll
        for (int ni = 0; ni < NI; ni++) {
            const int row = mb + mi * 16 + g;
            const int col = nb + ni * 8 + 2 * qd;
            if (DHALF) {
                __half* D = (__half*)Dv;
                *(__half2*)&D[(size_t)row * ldd + col] =
                    __floats2half2_rn(acc[mi][ni][0], acc[mi][ni][1]);
                *(__half2*)&D[(size_t)(row + 8) * ldd + col] =
                    __floats2half2_rn(acc[mi][ni][2], acc[mi][ni][3]);
            } else {
                float* D = (float*)Dv;
                *(float2*)&D[(size_t)row * ldd + col] =
                    make_float2(acc[mi][ni][0], acc[mi][ni][1]);
                *(float2*)&D[(size_t)(row + 8) * ldd + col] =
                    make_float2(acc[mi][ni][2], acc[mi][ni][3]);
            }
        }
}

// =============================================================================
// Conversion kernels
// =============================================================================
// qT[b][t][c] = fp16(q[b][c][t]) — 64c x 32t fp32 tile, uint4 half stores.
__global__ void __launch_bounds__(256) k_cvtqk(const float* __restrict__ q,
                                               const float* __restrict__ kk_)
{
    __shared__ float tile[64][33];
    const int z = blockIdx.z;
    const int b = z >> 1;
    const float* src = (z & 1) ? kk_ : q;
    __half* dst = (z & 1) ? g_kT : g_qT;
    const int t0 = blockIdx.x * 32;
    const int c0 = blockIdx.y * 64;
    const int tid = threadIdx.x;
    {
        const int x = tid & 31;
        const int y = tid >> 5;
#pragma unroll
        for (int j = 0; j < 8; j++) {
            int c = y + 8 * j;
            tile[c][x] = src[(size_t)b * CDIM * TDIM + (size_t)(c0 + c) * TDIM + t0 + x];
        }
    }
    __syncthreads();
    {
        const int t  = tid >> 3;
        const int c8 = (tid & 7) * 8;
        float f[8];
#pragma unroll
        for (int j = 0; j < 8; j++) f[j] = tile[c8 + j][t];
        __half2 h[4];
#pragma unroll
        for (int j = 0; j < 4; j++) h[j] = __floats2half2_rn(f[2 * j], f[2 * j + 1]);
        *(uint4*)&dst[(size_t)b * TDIM * CDIM + (size_t)(t0 + t) * CDIM + c0 + c8] =
            *(uint4*)h;
    }
}

// Merged auxiliary conversions: v, Wk, Wo linear + Wv transpose.
__global__ void __launch_bounds__(256) k_cvtaux(const float* __restrict__ v,
                                                const float* __restrict__ Wk,
                                                const float* __restrict__ Wo,
                                                const float* __restrict__ Wv)
{
    const int bx = blockIdx.x;
    const int tid = threadIdx.x;
    if (bx < 16896) {
        const float* src; __half* dst; size_t base;
        if (bx < 16384)      { src = v;  dst = g_vh;  base = (size_t)bx * 1024; }
        else if (bx < 16640) { src = Wk; dst = g_Wkh; base = (size_t)(bx - 16384) * 1024; }
        else                 { src = Wo; dst = g_Woh; base = (size_t)(bx - 16640) * 1024; }
        size_t off = base + (size_t)tid * 4;
        float4 a = *(const float4*)&src[off];
        *(__half2*)&dst[off]     = __floats2half2_rn(a.x, a.y);
        *(__half2*)&dst[off + 2] = __floats2half2_rn(a.z, a.w);
    } else {
        __shared__ float tile[64][33];
        const int idx = bx - 16896;
        const int t0 = (idx & 15) * 32;
        const int j0 = (idx >> 4) * 64;
        {
            const int x = tid & 31;
            const int y = tid >> 5;
#pragma unroll
            for (int jj = 0; jj < 8; jj++) {
                int j = y + 8 * jj;
                tile[j][x] = Wv[(size_t)(j0 + j) * TDIM + t0 + x];
            }
        }
        __syncthreads();
        {
            const int t  = tid >> 3;
            const int j8 = (tid & 7) * 8;
            float f[8];
#pragma unroll
            for (int jj = 0; jj < 8; jj++) f[jj] = tile[j8 + jj][t];
            __half2 h[4];
#pragma unroll
            for (int jj = 0; jj < 4; jj++)
                h[jj] = __floats2half2_rn(f[2 * jj], f[2 * jj + 1]);
            *(uint4*)&g_WvT[(size_t)(t0 + t) * TDIM + j0 + j8] = *(uint4*)h;
        }
    }
}

// =============================================================================
// K1: P half: g_Pd[b][t][ph*512+s] = sum_{c in half ph} qT[b][t][c] kT[b][s][c]
// Single launch, grid (4,4,16) = 256 CTAs.
// =============================================================================
__global__ void __launch_bounds__(256, 2) k_pmat()
{
    const int z  = blockIdx.z;
    const int b  = z >> 1;
    const int ph = z & 1;
    const int t0 = blockIdx.y * 128;
    const int s0 = blockIdx.x * 128;
    const __half* Ab = g_qT + (size_t)b * TDIM * CDIM + (size_t)t0 * CDIM + ph * (CDIM / 2);
    const __half* Bb = g_kT + (size_t)b * TDIM * CDIM + (size_t)s0 * CDIM + ph * (CDIM / 2);
    __half* D = g_Pd + (size_t)b * TDIM * 1024 + (size_t)t0 * 1024 + ph * 512 + s0;
    gemm_h<128, true>(Ab, CDIM, Bb, CDIM, 0xffffffffu, (CDIM / 2) / 32, D, 1024);
}

// =============================================================================
// K2a: U[b][t][hp*128 + e'] = sum_{k'=0..1023} g_Pd[b][t][k'] *
//      Wk[hp pair][e'][k' mod 512]          (2 heads per CTA, NCOLS=128)
// grid (4 t-tiles, 4 head-pairs, 8 b) = 128 CTAs, occ 2.
// =============================================================================
__global__ void __launch_bounds__(256, 2) k_umat()
{
    const int b  = blockIdx.z;
    const int hp = blockIdx.y;
    const int t0 = blockIdx.x * 128;
    const __half* Ab = g_Pd + (size_t)b * TDIM * 1024 + (size_t)t0 * 1024;
    const __half* Bb = g_Wkh + (size_t)hp * 128 * TDIM;
    float* D = g_U + (size_t)b * TDIM * 512 + (size_t)t0 * 512 + hp * 128;
    gemm_h<128, false>(Ab, 1024, Bb, TDIM, 511u, 1024 / 32, D, 512);
}

// =============================================================================
// K2b: per (b,h): S = Wq_h @ U_h / sqrt(512); W = softmax_rows(S);
// store W^T fp16 -> g_W[bh][e][d].   U stride 512 (heads packed).
// =============================================================================
__global__ void __launch_bounds__(256) k_attn(const float* __restrict__ Wq)
{
    const int bh = blockIdx.x;
    const int b = bh >> 3, h = bh & 7;

    __shared__ float Ws[64][65];
    __shared__ float Us[32][68];
    __shared__ float Wqs[64][33];

    const float* Ub  = g_U + (size_t)b * TDIM * 512 + h * 64;
    const float* Wqh = Wq + (size_t)h * HDIM * TDIM;

    const int tid = threadIdx.x;
    const int tx = tid & 15, ty = tid >> 4;

    float acc[4][4];
#pragma unroll
    for (int m = 0; m < 4; m++)
#pragma unroll
        for (int n = 0; n < 4; n++) acc[m][n] = 0.f;

    for (int t0 = 0; t0 < TDIM; t0 += 32) {
#pragma unroll
        for (int i = 0; i < 2; i++) {
            int idx = tid + i * 256;
            int tl  = idx >> 4;
            int eq  = (idx & 15) * 4;
            *(float4*)&Us[tl][eq] = *(const float4*)&Ub[(size_t)(t0 + tl) * 512 + eq];
        }
#pragma unroll
        for (int i = 0; i < 2; i++) {
            int idx = tid + i * 256;
            int d   = idx >> 3;
            int tq  = (idx & 7) * 4;
            float4 a = *(const float4*)&Wqh[(size_t)d * TDIM + t0 + tq];
            Wqs[d][tq + 0] = a.x; Wqs[d][tq + 1] = a.y;
            Wqs[d][tq + 2] = a.z; Wqs[d][tq + 3] = a.w;
        }
        __syncthreads();
#pragma unroll
        for (int tl = 0; tl < 32; tl++) {
            float ra[4], rb[4];
#pragma unroll
            for (int m = 0; m < 4; m++) ra[m] = Wqs[ty * 4 + m][tl];
#pragma unroll
            for (int n = 0; n < 4; n++) rb[n] = Us[tl][tx * 4 + n];
#pragma unroll
            for (int m = 0; m < 4; m++)
#pragma unroll
                for (int n = 0; n < 4; n++) acc[m][n] += ra[m] * rb[n];
        }
        __syncthreads();
    }

#pragma unroll
    for (int m = 0; m < 4; m++)
#pragma unroll
        for (int n = 0; n < 4; n++)
            Ws[ty * 4 + m][tx * 4 + n] = acc[m][n] * SCALE_INV;
    __syncthreads();

    if (tid < 64) {
        float mx = -1e30f;
#pragma unroll 8
        for (int e = 0; e < 64; e++) mx = fmaxf(mx, Ws[tid][e]);
        float sum = 0.f;
#pragma unroll 8
        for (int e = 0; e < 64; e++) { float ex = expf(Ws[tid][e] - mx); Ws[tid][e] = ex; sum += ex; }
        float inv = 1.f / sum;
#pragma unroll 8
        for (int e = 0; e < 64; e++) Ws[tid][e] *= inv;
    }
    __syncthreads();

    __half* Wt = g_W + (size_t)bh * HDIM * HDIM;
    for (int idx = tid; idx < HDIM * HDIM; idx += 256) {
        int e = idx >> 6, d = idx & 63;
        Wt[(size_t)e * HDIM + d] = __float2half_rn(Ws[d][e]);
    }
}

// =============================================================================
// K2c: Z[b][o][h*64+e] = sum_d Wo[o][h*64+d] * W_h[d][e]
// =============================================================================
__global__ void __launch_bounds__(256, 3) k_zmat()
{
    const int bh = blockIdx.y;
    const int b = bh >> 3, h = bh & 7;
    const int o0 = blockIdx.x * 128;
    const __half* Ab = g_Woh + (size_t)o0 * (NH * HDIM) + h * HDIM;
    const __half* Bb = g_W + (size_t)bh * HDIM * HDIM;
    __half* D = g_Z + (size_t)b * TDIM * TDIM + (size_t)o0 * TDIM + h * HDIM;
    gemm_h<64, true>(Ab, NH * HDIM, Bb, HDIM, 0xffffffffu, HDIM / 32, D, TDIM);
}

// =============================================================================
// K3: G[b][o][t] = sum_j Z[b][o][j] * WvT[t][j]
// =============================================================================
__global__ void __launch_bounds__(256, 3) k_gmat()
{
    const int b  = blockIdx.z;
    const int o0 = blockIdx.y * 128;
    const int t0 = blockIdx.x * 64;
    const __half* Ab = g_Z + (size_t)b * TDIM * TDIM + (size_t)o0 * TDIM;
    const __half* Bb = g_WvT + (size_t)t0 * TDIM;
    __half* D = g_G + (size_t)b * TDIM * TDIM + (size_t)o0 * TDIM + t0;
    gemm_h<64, true>(Ab, TDIM, Bb, TDIM, 0xffffffffu, TDIM / 32, D, TDIM);
}

// =============================================================================
// K4: out[b][c][o] = sum_t vh[b][c][t] * G[b][o][t]
// =============================================================================
__global__ void __launch_bounds__(256, 2) k_out(float* __restrict__ out)
{
    const int b  = blockIdx.z;
    const int c0 = blockIdx.y * 128;
    const int o0 = blockIdx.x * 128;
    const __half* Ab = g_vh + (size_t)b * CDIM * TDIM + (size_t)c0 * TDIM;
    const __half* Bb = g_G + (size_t)b * TDIM * TDIM + (size_t)o0 * TDIM;
    float* D = out + (size_t)b * CDIM * ODIM + (size_t)c0 * ODIM + o0;
    gemm_h<128, false>(Ab, TDIM, Bb, TDIM, 0xffffffffu, TDIM / 32, D, ODIM);
}

// =============================================================================
extern "C" void kernel_launch(void* const* d_in, const int* in_sizes, int n_in,
                              void* d_out, int out_size)
{
    const float* q  = (const float*)d_in[0];
    const float* k  = (const float*)d_in[1];
    const float* v  = (const float*)d_in[2];
    const float* Wq = (const float*)d_in[3];
    const float* Wk = (const float*)d_in[4];
    const float* Wv = (const float*)d_in[5];
    const float* Wo = (const float*)d_in[6];
    float* out = (float*)d_out;
    (void)in_sizes; (void)n_in; (void)out_size;

    const int SM_128 = 3 * (128 + 128) * 32 * 2;   // 49152
    const int SM_64  = 3 * (128 + 64) * 32 * 2;    // 36864

    cudaFuncSetAttribute(k_pmat, cudaFuncAttributeMaxDynamicSharedMemorySize, SM_128);
    cudaFuncSetAttribute(k_umat, cudaFuncAttributeMaxDynamicSharedMemorySize, SM_128);
    cudaFuncSetAttribute(k_zmat, cudaFuncAttributeMaxDynamicSharedMemorySize, SM_64);
    cudaFuncSetAttribute(k_gmat, cudaFuncAttributeMaxDynamicSharedMemorySize, SM_64);
    cudaFuncSetAttribute(k_out,  cudaFuncAttributeMaxDynamicSharedMemorySize, SM_128);

    // Side stream + events (host objects; created once).
    static cudaStream_t s_side = nullptr;
    static cudaEvent_t  s_fork = nullptr, s_join = nullptr;
    if (s_side == nullptr) {
        cudaStreamCreateWithFlags(&s_side, cudaStreamNonBlocking);
        cudaEventCreateWithFlags(&s_fork, cudaEventDisableTiming);
        cudaEventCreateWithFlags(&s_join, cudaEventDisableTiming);
    }

    // Fork: aux conversions run concurrently with cvtqk + pmat.
    cudaEventRecord(s_fork, 0);
    cudaStreamWaitEvent(s_side, s_fork, 0);
    k_cvtaux<<<17024, 256, 0, s_side>>>(v, Wk, Wo, Wv);
    cudaEventRecord(s_join, s_side);

    // Main chain
    k_cvtqk<<<dim3(16, 64, 16), 256>>>(q, k);
    k_pmat<<<dim3(4, 4, BSZ * 2), 256, SM_128>>>();

    // Join: umat (and later kernels) need aux outputs.
    cudaStreamWaitEvent(0, s_join, 0);

    k_umat<<<dim3(4, 4, BSZ),   256, SM_128>>>();
    k_attn<<<BSZ * NH,          256>>>(Wq);
    k_zmat<<<dim3(4, BSZ * NH), 256, SM_64>>>();
    k_gmat<<<dim3(8, 4, BSZ),   256, SM_64>>>();
    k_out <<<dim3(4, 32, BSZ),  256, SM_128>>>(out);
}